// round 6
// baseline (speedup 1.0000x reference)
#include <cuda_runtime.h>
#include <cuda_fp16.h>
#include <cstdint>
#include <math.h>

#define BB 2
#define SS 2048
#define DM 1024
#define NH 16
#define HD 64

// fp16 scratch (device globals: allocation-free per harness rules)
__device__ __half g_q[BB * NH * SS * HD];     // [b][h][s][c], pre-scaled by 0.125*log2e
__device__ __half g_k[BB * NH * SS * HD];
__device__ __half g_v[BB * NH * SS * HD];
__device__ __half g_vals[BB * SS * DM];
__device__ __half g_xh[BB * SS * DM];
__device__ __half g_yh[BB * SS * DM];
__device__ __half g_wq[DM * DM];
__device__ __half g_wkv[DM * 2 * DM];
__device__ __half g_wo[DM * DM];
__device__ __half g_maskh[BB * SS * SS];      // mask * log2e

// ---------------------------------------------------------------------------
// helpers
// ---------------------------------------------------------------------------
__device__ __forceinline__ unsigned pkh(float a, float b) {
    __half2 h = __floats2half2_rn(a, b);
    return *reinterpret_cast<unsigned*>(&h);
}
__device__ __forceinline__ unsigned sptr(const void* p) {
    return (unsigned)__cvta_generic_to_shared(p);
}
__device__ __forceinline__ void ldsm4(unsigned* r, unsigned addr) {
    asm volatile("ldmatrix.sync.aligned.m8n8.x4.shared.b16 {%0,%1,%2,%3},[%4];"
                 : "=r"(r[0]), "=r"(r[1]), "=r"(r[2]), "=r"(r[3]) : "r"(addr));
}
__device__ __forceinline__ void ldsm4t(unsigned* r, unsigned addr) {
    asm volatile("ldmatrix.sync.aligned.m8n8.x4.trans.shared.b16 {%0,%1,%2,%3},[%4];"
                 : "=r"(r[0]), "=r"(r[1]), "=r"(r[2]), "=r"(r[3]) : "r"(addr));
}
__device__ __forceinline__ void mma16(float* d, const unsigned* a, const unsigned* b) {
    asm volatile(
        "mma.sync.aligned.m16n8k16.row.col.f32.f16.f16.f32 "
        "{%0,%1,%2,%3},{%4,%5,%6,%7},{%8,%9},{%0,%1,%2,%3};"
        : "+f"(d[0]), "+f"(d[1]), "+f"(d[2]), "+f"(d[3])
        : "r"(a[0]), "r"(a[1]), "r"(a[2]), "r"(a[3]), "r"(b[0]), "r"(b[1]));
}
__device__ __forceinline__ float ex2(float x) {
    float y;
    asm("ex2.approx.ftz.f32 %0, %1;" : "=f"(y) : "f"(x));
    return y;
}

// ---------------------------------------------------------------------------
// fp32 -> fp16 convert (optionally scaled), vectorized x4
// ---------------------------------------------------------------------------
__global__ __launch_bounds__(256)
void cvt_h(const float4* __restrict__ src, uint2* __restrict__ dst, int n4, float scale)
{
    const int i = blockIdx.x * blockDim.x + threadIdx.x;
    if (i < n4) {
        const float4 v = src[i];
        uint2 o;
        o.x = pkh(v.x * scale, v.y * scale);
        o.y = pkh(v.z * scale, v.w * scale);
        dst[i] = o;
    }
}

// ---------------------------------------------------------------------------
// epilogue scatter
// ---------------------------------------------------------------------------
#define QSCALE 0.1803368801111244f  /* 0.125 * log2(e) */

template <int MODE>
__device__ __forceinline__ void store2(int r, int c0, float v0, float v1,
                                       float* __restrict__ Cout, int N)
{
    const int b = r >> 11;
    const int s = r & 2047;
    if (MODE == 0) {
        const int h = c0 >> 6, cc = c0 & 63;
        const size_t idx = (((size_t)(b * NH + h) * SS) + s) * HD + cc;
        *(unsigned*)&g_q[idx] = pkh(v0 * QSCALE, v1 * QSCALE);
    } else if (MODE == 1) {
        const int h = c0 >> 7, t = c0 & 127;
        if (t < HD) {
            const size_t idx = (((size_t)(b * NH + h) * SS) + s) * HD + t;
            *(unsigned*)&g_k[idx] = pkh(v0, v1);
        } else {
            const size_t idx = (((size_t)(b * NH + h) * SS) + s) * HD + (t - HD);
            *(unsigned*)&g_v[idx] = pkh(v0, v1);
        }
    } else {
        *(float2*)&Cout[(size_t)r * N + c0] = make_float2(v0, v1);
    }
}

// ---------------------------------------------------------------------------
// Double-buffered all-fp16 GEMM core. 128x128 tile, K-chunk 32, 8 warps
// (2m x 4n), warp tile 64x32, mma.m16n8k16 + ldmatrix. One sync per chunk.
// ---------------------------------------------------------------------------
template <int MODE>
__device__ __forceinline__ void gemm_core(
    const __half* __restrict__ Ah, const __half* __restrict__ Wh,
    const float* __restrict__ bias, float* __restrict__ Cout,
    int N, int K, int brow, int bcol,
    __half (*As)[40], __half (*Bs)[136])
{
    const int tid  = threadIdx.x;
    const int lane = tid & 31;
    const int w    = tid >> 5;
    const int wm   = (w >> 2) * 64;
    const int wn   = (w & 3) * 32;

    const int ar = tid >> 1;            // 0..127
    const int ac = (tid & 1) * 16;      // 0,16
    const int br = tid >> 3;            // 0..31
    const int bc = (tid & 7) * 16;      // 0..112

    float acc[4][4][4];
#pragma unroll
    for (int mi = 0; mi < 4; mi++)
#pragma unroll
        for (int ni = 0; ni < 4; ni++)
#pragma unroll
            for (int e = 0; e < 4; e++) acc[mi][ni][e] = 0.f;

    uint4 pah[2], pwh[2];

    // prefetch chunk 0
    pah[0] = *(const uint4*)(Ah + (size_t)(brow + ar) * K + ac);
    pah[1] = *(const uint4*)(Ah + (size_t)(brow + ar) * K + ac + 8);
    pwh[0] = *(const uint4*)(Wh + (size_t)br * N + bcol + bc);
    pwh[1] = *(const uint4*)(Wh + (size_t)br * N + bcol + bc + 8);

    // store chunk 0 into buffer 0
    *(uint4*)&As[ar][ac]     = pah[0];
    *(uint4*)&As[ar][ac + 8] = pah[1];
    *(uint4*)&Bs[br][bc]     = pwh[0];
    *(uint4*)&Bs[br][bc + 8] = pwh[1];

    const int NC = K / 32;
    for (int c = 0; c < NC; c++) {
        __syncthreads();

        // prefetch chunk c+1 (overlaps compute)
        if (c + 1 < NC) {
            const int kn = (c + 1) * 32;
            pah[0] = *(const uint4*)(Ah + (size_t)(brow + ar) * K + kn + ac);
            pah[1] = *(const uint4*)(Ah + (size_t)(brow + ar) * K + kn + ac + 8);
            pwh[0] = *(const uint4*)(Wh + (size_t)(kn + br) * N + bcol + bc);
            pwh[1] = *(const uint4*)(Wh + (size_t)(kn + br) * N + bcol + bc + 8);
        }

        // compute on buffer (c & 1)
        const int aoff = (c & 1) * 128;
        const int boff = (c & 1) * 32;
#pragma unroll
        for (int ks2 = 0; ks2 < 2; ks2++) {
            const int kk = ks2 * 16;
            unsigned af[4][4];
#pragma unroll
            for (int mi = 0; mi < 4; mi++)
                ldsm4(af[mi], sptr(&As[aoff + wm + mi * 16 + (lane & 15)][kk + ((lane >> 4) << 3)]));
            unsigned bfr[2][4];
#pragma unroll
            for (int np = 0; np < 2; np++) {
                const int row = boff + kk + (lane & 7) + (((lane >> 3) & 1) << 3);
                const int col = wn + np * 16 + ((lane >> 4) << 3);
                ldsm4t(bfr[np], sptr(&Bs[row][col]));
            }
#pragma unroll
            for (int mi = 0; mi < 4; mi++)
#pragma unroll
                for (int ni = 0; ni < 4; ni++)
                    mma16(acc[mi][ni], af[mi], &bfr[ni >> 1][(ni & 1) * 2]);
        }

        // store chunk c+1 into other buffer
        if (c + 1 < NC) {
            const int ao = ((c + 1) & 1) * 128;
            const int bo = ((c + 1) & 1) * 32;
            *(uint4*)&As[ao + ar][ac]     = pah[0];
            *(uint4*)&As[ao + ar][ac + 8] = pah[1];
            *(uint4*)&Bs[bo + br][bc]     = pwh[0];
            *(uint4*)&Bs[bo + br][bc + 8] = pwh[1];
        }
    }

    // epilogue
    const int g = lane >> 2, q = lane & 3;
#pragma unroll
    for (int mi = 0; mi < 4; mi++) {
        const int r0 = brow + wm + mi * 16 + g;
        const int r1 = r0 + 8;
#pragma unroll
        for (int ni = 0; ni < 4; ni++) {
            const int c0 = bcol + wn + ni * 8 + 2 * q;
            const float bia0 = bias[c0], bia1 = bias[c0 + 1];
            store2<MODE>(r0, c0, acc[mi][ni][0] + bia0, acc[mi][ni][1] + bia1, Cout, N);
            store2<MODE>(r1, c0, acc[mi][ni][2] + bia0, acc[mi][ni][3] + bia1, Cout, N);
        }
    }
}

// ---------------------------------------------------------------------------
// Fused q + kv projection: grid.x = 8 (q tiles) + 16 (kv tiles) = 24
// ---------------------------------------------------------------------------
__global__ __launch_bounds__(256)
void proj_fused(const float* __restrict__ bq, const float* __restrict__ bkv)
{
    __shared__ __half As[2 * 128][40];
    __shared__ __half Bs[2 * 32][136];

    const int brow = blockIdx.y * 128;
    if (blockIdx.x < 8) {
        gemm_core<0>(g_yh, g_wq, bq, nullptr, DM, DM, brow, blockIdx.x * 128, As, Bs);
    } else {
        gemm_core<1>(g_xh, g_wkv, bkv, nullptr, 2 * DM, DM, brow, (blockIdx.x - 8) * 128, As, Bs);
    }
}

// ---------------------------------------------------------------------------
// Output projection: A = g_vals (fp16), fp32 out
// ---------------------------------------------------------------------------
__global__ __launch_bounds__(256)
void gemm_o(const float* __restrict__ bias, float* __restrict__ Cout)
{
    __shared__ __half As[2 * 128][40];
    __shared__ __half Bs[2 * 32][136];
    gemm_core<2>(g_vals, g_wo, bias, Cout, DM, DM,
                 blockIdx.y * 128, blockIdx.x * 128, As, Bs);
}

// ---------------------------------------------------------------------------
// Flash attention fp16, double-buffered K/V tiles, one sync per tile.
// 128 q-rows/CTA, 8 warps, key tile 64. Scores in log2e space; ex2 softmax.
// ---------------------------------------------------------------------------
__global__ __launch_bounds__(256)
void attn_h()
{
    extern __shared__ __half smh[];
    __half (*qs)[72] = (__half(*)[72])smh;                   // 128 x 72
    __half (*ks)[72] = (__half(*)[72])(smh + 128 * 72);      // 2 x 64 x 72
    __half (*vs)[72] = (__half(*)[72])(smh + 128 * 72 + 2 * 64 * 72);

    const int tid  = threadIdx.x;
    const int lane = tid & 31;
    const int w    = tid >> 5;
    const int g    = lane >> 2;
    const int q    = lane & 3;

    const int bh    = blockIdx.y;
    const int b     = bh >> 4;
    const int h     = bh & 15;
    const int qbase = blockIdx.x * 128;

    const __half* qg  = g_q + ((size_t)bh * SS + qbase) * HD;
    const __half* kgb = g_k + (size_t)bh * SS * HD;
    const __half* vgb = g_v + (size_t)bh * SS * HD;

    // load q tile (already fp16 + pre-scaled by 0.125*log2e)
    {
        const int r = tid >> 1, cs = (tid & 1) * 32;
#pragma unroll
        for (int i = 0; i < 4; i++)
            *(uint4*)&qs[r][cs + i * 8] = *(const uint4*)(qg + (size_t)r * HD + cs + i * 8);
    }

    const int tr = tid >> 2;            // 0..63
    const int tc = (tid & 3) * 16;      // 0,16,32,48

    // prefetch tile 0 and store into buffer 0
    uint4 kreg[2], vreg[2];
#pragma unroll
    for (int i = 0; i < 2; i++) {
        kreg[i] = *(const uint4*)(kgb + (size_t)tr * HD + tc + i * 8);
        vreg[i] = *(const uint4*)(vgb + (size_t)tr * HD + tc + i * 8);
    }
    *(uint4*)&ks[tr][tc]     = kreg[0];
    *(uint4*)&ks[tr][tc + 8] = kreg[1];
    *(uint4*)&vs[tr][tc]     = vreg[0];
    *(uint4*)&vs[tr][tc + 8] = vreg[1];

    __syncthreads();

    // hoist q a-fragments
    unsigned qa[4][4];
#pragma unroll
    for (int kk4 = 0; kk4 < 4; kk4++)
        ldsm4(qa[kk4], sptr(&qs[w * 16 + (lane & 15)][kk4 * 16 + ((lane >> 4) << 3)]));

    float oacc[8][4];
#pragma unroll
    for (int ni = 0; ni < 8; ni++)
#pragma unroll
        for (int e = 0; e < 4; e++) oacc[ni][e] = 0.f;
    float m0 = -1e30f, m1 = -1e30f, l0 = 0.f, l1 = 0.f;

    const int qrow0 = w * 16 + g;
    const int qrow1 = qrow0 + 8;
    const __half* mrow0 = g_maskh + ((size_t)b * SS + qbase + qrow0) * SS;
    const __half* mrow1 = g_maskh + ((size_t)b * SS + qbase + qrow1) * SS;

    const int NT = SS / 64;
    for (int kt = 0; kt < NT; kt++) {
        const int kbase = kt * 64;
        const int cb = (kt & 1) * 64;
        const int nb = ((kt + 1) & 1) * 64;

        if (kt + 1 < NT) {
            const size_t off = (size_t)(kbase + 64 + tr) * HD + tc;
#pragma unroll
            for (int i = 0; i < 2; i++) {
                kreg[i] = *(const uint4*)(kgb + off + i * 8);
                vreg[i] = *(const uint4*)(vgb + off + i * 8);
            }
        }

        // ---- S = Q K^T (log2e-scaled)
        float sacc[8][4];
#pragma unroll
        for (int ni = 0; ni < 8; ni++)
#pragma unroll
            for (int e = 0; e < 4; e++) sacc[ni][e] = 0.f;

#pragma unroll
        for (int kk4 = 0; kk4 < 4; kk4++) {
#pragma unroll
            for (int np = 0; np < 4; np++) {
                unsigned kb[4];
                const int row = cb + np * 16 + (lane & 7) + (((lane >> 4) & 1) << 3);
                const int col = kk4 * 16 + (((lane >> 3) & 1) << 3);
                ldsm4(kb, sptr(&ks[row][col]));
                mma16(sacc[np * 2],     qa[kk4], &kb[0]);
                mma16(sacc[np * 2 + 1], qa[kk4], &kb[2]);
            }
        }

        // ---- + mask (fp16, pre-scaled by log2e)
#pragma unroll
        for (int ni = 0; ni < 8; ni++) {
            const int col = kbase + ni * 8 + 2 * q;
            const __half2 mh0 = *(const __half2*)(mrow0 + col);
            const __half2 mh1 = *(const __half2*)(mrow1 + col);
            const float2 mv0 = __half22float2(mh0);
            const float2 mv1 = __half22float2(mh1);
            sacc[ni][0] += mv0.x; sacc[ni][1] += mv0.y;
            sacc[ni][2] += mv1.x; sacc[ni][3] += mv1.y;
        }

        // ---- online softmax (base-2)
        float mx0 = -1e30f, mx1 = -1e30f;
#pragma unroll
        for (int ni = 0; ni < 8; ni++) {
            mx0 = fmaxf(mx0, fmaxf(sacc[ni][0], sacc[ni][1]));
            mx1 = fmaxf(mx1, fmaxf(sacc[ni][2], sacc[ni][3]));
        }
        mx0 = fmaxf(mx0, __shfl_xor_sync(0xffffffffu, mx0, 1));
        mx0 = fmaxf(mx0, __shfl_xor_sync(0xffffffffu, mx0, 2));
        mx1 = fmaxf(mx1, __shfl_xor_sync(0xffffffffu, mx1, 1));
        mx1 = fmaxf(mx1, __shfl_xor_sync(0xffffffffu, mx1, 2));

        const float mn0 = fmaxf(m0, mx0);
        const float mn1 = fmaxf(m1, mx1);
        const float al0 = ex2(m0 - mn0);
        const float al1 = ex2(m1 - mn1);
        float sum0 = 0.f, sum1 = 0.f;
#pragma unroll
        for (int ni = 0; ni < 8; ni++) {
            sacc[ni][0] = ex2(sacc[ni][0] - mn0); sum0 += sacc[ni][0];
            sacc[ni][1] = ex2(sacc[ni][1] - mn0); sum0 += sacc[ni][1];
            sacc[ni][2] = ex2(sacc[ni][2] - mn1); sum1 += sacc[ni][2];
            sacc[ni][3] = ex2(sacc[ni][3] - mn1); sum1 += sacc[ni][3];
        }
        sum0 += __shfl_xor_sync(0xffffffffu, sum0, 1);
        sum0 += __shfl_xor_sync(0xffffffffu, sum0, 2);
        sum1 += __shfl_xor_sync(0xffffffffu, sum1, 1);
        sum1 += __shfl_xor_sync(0xffffffffu, sum1, 2);
        l0 = l0 * al0 + sum0; m0 = mn0;
        l1 = l1 * al1 + sum1; m1 = mn1;

#pragma unroll
        for (int ni = 0; ni < 8; ni++) {
            oacc[ni][0] *= al0; oacc[ni][1] *= al0;
            oacc[ni][2] *= al1; oacc[ni][3] *= al1;
        }

        // ---- O += P V
#pragma unroll
        for (int j = 0; j < 4; j++) {
            unsigned paf[4];
            paf[0] = pkh(sacc[2 * j][0],     sacc[2 * j][1]);
            paf[1] = pkh(sacc[2 * j][2],     sacc[2 * j][3]);
            paf[2] = pkh(sacc[2 * j + 1][0], sacc[2 * j + 1][1]);
            paf[3] = pkh(sacc[2 * j + 1][2], sacc[2 * j + 1][3]);
#pragma unroll
            for (int np = 0; np < 4; np++) {
                unsigned vb[4];
                const int row = cb + j * 16 + (lane & 7) + (((lane >> 3) & 1) << 3);
                const int col = np * 16 + ((lane >> 4) << 3);
                ldsm4t(vb, sptr(&vs[row][col]));
                mma16(oacc[np * 2],     paf, &vb[0]);
                mma16(oacc[np * 2 + 1], paf, &vb[2]);
            }
        }

        if (kt + 1 < NT) {
            *(uint4*)&ks[nb + tr][tc]     = kreg[0];
            *(uint4*)&ks[nb + tr][tc + 8] = kreg[1];
            *(uint4*)&vs[nb + tr][tc]     = vreg[0];
            *(uint4*)&vs[nb + tr][tc + 8] = vreg[1];
            __syncthreads();
        }
    }

    // epilogue -> g_vals (half, B,S,D layout)
    const float inv0 = 1.0f / l0;
    const float inv1 = 1.0f / l1;
    __half* orow0 = g_vals + ((size_t)b * SS + qbase + qrow0) * DM + h * HD;
    __half* orow1 = g_vals + ((size_t)b * SS + qbase + qrow1) * DM + h * HD;
#pragma unroll
    for (int ni = 0; ni < 8; ni++) {
        const int col = ni * 8 + 2 * q;
        *(unsigned*)&orow0[col] = pkh(oacc[ni][0] * inv0, oacc[ni][1] * inv0);
        *(unsigned*)&orow1[col] = pkh(oacc[ni][2] * inv1, oacc[ni][3] * inv1);
    }
}

// ---------------------------------------------------------------------------
extern "C" void kernel_launch(void* const* d_in, const int* in_sizes, int n_in,
                              void* d_out, int out_size)
{
    const float* x    = (const float*)d_in[0];
    const float* y    = (const float*)d_in[1];
    const float* mask = (const float*)d_in[2];
    const float* Wkv  = (const float*)d_in[3];
    const float* bkv  = (const float*)d_in[4];
    const float* Wq   = (const float*)d_in[5];
    const float* bq   = (const float*)d_in[6];
    const float* Wo   = (const float*)d_in[7];
    const float* bo   = (const float*)d_in[8];
    float* out = (float*)d_out;

    void *xh, *yh, *wq, *wkv, *wo, *mh;
    cudaGetSymbolAddress(&xh, g_xh);
    cudaGetSymbolAddress(&yh, g_yh);
    cudaGetSymbolAddress(&wq, g_wq);
    cudaGetSymbolAddress(&wkv, g_wkv);
    cudaGetSymbolAddress(&wo, g_wo);
    cudaGetSymbolAddress(&mh, g_maskh);

    const dim3 blk(256);
    const int M = BB * SS;  // 4096
    const float LOG2E = 1.4426950408889634f;

    // fp32 -> fp16 pre-passes
    cvt_h<<<(BB * SS * DM / 4 + 255) / 256, blk>>>((const float4*)x,  (uint2*)xh,  BB * SS * DM / 4, 1.f);
    cvt_h<<<(BB * SS * DM / 4 + 255) / 256, blk>>>((const float4*)y,  (uint2*)yh,  BB * SS * DM / 4, 1.f);
    cvt_h<<<(DM * DM / 4 + 255) / 256, blk>>>((const float4*)Wq,  (uint2*)wq,  DM * DM / 4, 1.f);
    cvt_h<<<(DM * 2 * DM / 4 + 255) / 256, blk>>>((const float4*)Wkv, (uint2*)wkv, DM * 2 * DM / 4, 1.f);
    cvt_h<<<(DM * DM / 4 + 255) / 256, blk>>>((const float4*)Wo,  (uint2*)wo,  DM * DM / 4, 1.f);
    cvt_h<<<(BB * SS * SS / 4 + 255) / 256, blk>>>((const float4*)mask, (uint2*)mh, BB * SS * SS / 4, LOG2E);

    // fused q + kv projection
    proj_fused<<<dim3(24, M / 128), blk>>>(bq, bkv);

    // attention
    const int smem_attn = (128 * 72 + 4 * 64 * 72) * (int)sizeof(__half);
    cudaFuncSetAttribute(attn_h, cudaFuncAttributeMaxDynamicSharedMemorySize, smem_attn);
    attn_h<<<dim3(SS / 128, BB * NH), blk, smem_attn>>>();

    // output projection
    gemm_o<<<dim3(DM / 128, M / 128), blk>>>(bo, out);
}

// round 8
// speedup vs baseline: 1.3929x; 1.3929x over previous
#include <cuda_runtime.h>
#include <cuda_fp16.h>
#include <cstdint>
#include <math.h>

#define BB 2
#define SS 2048
#define DM 1024
#define NH 16
#define HD 64

// fp16 scratch (device globals: allocation-free per harness rules)
__device__ __half g_q[BB * NH * SS * HD];     // [b][h][s][c], pre-scaled by 0.125*log2e
__device__ __half g_k[BB * NH * SS * HD];
__device__ __half g_v[BB * NH * SS * HD];
__device__ __half g_vals[BB * SS * DM];
__device__ __half g_xh[BB * SS * DM];
__device__ __half g_yh[BB * SS * DM];
__device__ __half g_wq[DM * DM];              // fp16, [K][N] row-major
__device__ __half g_wkv[DM * 2 * DM];
__device__ __half g_wo[DM * DM];
__device__ int    g_mask_nz;                  // 0 if mask is all zeros

// ---------------------------------------------------------------------------
// helpers
// ---------------------------------------------------------------------------
__device__ __forceinline__ unsigned pkh(float a, float b) {
    __half2 h = __floats2half2_rn(a, b);
    return *reinterpret_cast<unsigned*>(&h);
}
__device__ __forceinline__ unsigned sptr(const void* p) {
    return (unsigned)__cvta_generic_to_shared(p);
}
__device__ __forceinline__ void ldsm4(unsigned* r, unsigned addr) {
    asm volatile("ldmatrix.sync.aligned.m8n8.x4.shared.b16 {%0,%1,%2,%3},[%4];"
                 : "=r"(r[0]), "=r"(r[1]), "=r"(r[2]), "=r"(r[3]) : "r"(addr));
}
__device__ __forceinline__ void ldsm4t(unsigned* r, unsigned addr) {
    asm volatile("ldmatrix.sync.aligned.m8n8.x4.trans.shared.b16 {%0,%1,%2,%3},[%4];"
                 : "=r"(r[0]), "=r"(r[1]), "=r"(r[2]), "=r"(r[3]) : "r"(addr));
}
__device__ __forceinline__ void mma16(float* d, const unsigned* a, const unsigned* b) {
    asm volatile(
        "mma.sync.aligned.m16n8k16.row.col.f32.f16.f16.f32 "
        "{%0,%1,%2,%3},{%4,%5,%6,%7},{%8,%9},{%0,%1,%2,%3};"
        : "+f"(d[0]), "+f"(d[1]), "+f"(d[2]), "+f"(d[3])
        : "r"(a[0]), "r"(a[1]), "r"(a[2]), "r"(a[3]), "r"(b[0]), "r"(b[1]));
}
__device__ __forceinline__ float ex2(float x) {
    float y;
    asm("ex2.approx.ftz.f32 %0, %1;" : "=f"(y) : "f"(x));
    return y;
}
// cp.async 16B
__device__ __forceinline__ void cp16(unsigned dst, const void* src) {
    asm volatile("cp.async.cg.shared.global [%0], [%1], 16;"
                 :: "r"(dst), "l"(src) : "memory");
}
__device__ __forceinline__ void cp_commit() {
    asm volatile("cp.async.commit_group;" ::: "memory");
}
template <int N>
__device__ __forceinline__ void cp_wait() {
    asm volatile("cp.async.wait_group %0;" :: "n"(N) : "memory");
}

// ---------------------------------------------------------------------------
// pre-passes
// ---------------------------------------------------------------------------
__global__ __launch_bounds__(256)
void cvt_h(const float4* __restrict__ src, uint2* __restrict__ dst, int n4, float scale)
{
    const int i = blockIdx.x * blockDim.x + threadIdx.x;
    if (i < n4) {
        const float4 v = src[i];
        uint2 o;
        o.x = pkh(v.x * scale, v.y * scale);
        o.y = pkh(v.z * scale, v.w * scale);
        dst[i] = o;
    }
}

__global__ void flag_zero() { g_mask_nz = 0; }

__global__ __launch_bounds__(256)
void mask_check(const float4* __restrict__ m, int n4)
{
    const int i = blockIdx.x * blockDim.x + threadIdx.x;
    if (i < n4) {
        const float4 v = m[i];
        if (v.x != 0.f || v.y != 0.f || v.z != 0.f || v.w != 0.f)
            atomicOr(&g_mask_nz, 1);
    }
}

// ---------------------------------------------------------------------------
// epilogue scatter
// ---------------------------------------------------------------------------
#define QSCALE 0.1803368801111244f  /* 0.125 * log2(e) */
#define LOG2E  1.4426950408889634f

template <int MODE>
__device__ __forceinline__ void store2(int r, int c0, float v0, float v1,
                                       float* __restrict__ Cout, int N)
{
    const int b = r >> 11;
    const int s = r & 2047;
    if (MODE == 0) {
        const int h = c0 >> 6, cc = c0 & 63;
        const size_t idx = (((size_t)(b * NH + h) * SS) + s) * HD + cc;
        *(unsigned*)&g_q[idx] = pkh(v0 * QSCALE, v1 * QSCALE);
    } else if (MODE == 1) {
        const int h = c0 >> 7, t = c0 & 127;
        if (t < HD) {
            const size_t idx = (((size_t)(b * NH + h) * SS) + s) * HD + t;
            *(unsigned*)&g_k[idx] = pkh(v0, v1);
        } else {
            const size_t idx = (((size_t)(b * NH + h) * SS) + s) * HD + (t - HD);
            *(unsigned*)&g_v[idx] = pkh(v0, v1);
        }
    } else {
        *(float2*)&Cout[(size_t)r * N + c0] = make_float2(v0, v1);
    }
}

// ---------------------------------------------------------------------------
// cp.async double-buffered fp16 GEMM core. 128x128 tile, K-chunk 32, 8 warps
// (2m x 4n), warp tile 64x32, mma.m16n8k16 + ldmatrix. One sync per chunk.
// ---------------------------------------------------------------------------
template <int MODE>
__device__ __forceinline__ void gemm_core(
    const __half* __restrict__ Ah, const __half* __restrict__ Wh,
    const float* __restrict__ bias, float* __restrict__ Cout,
    int N, int K, int brow, int bcol,
    __half (*As)[40], __half (*Bs)[136])
{
    const int tid  = threadIdx.x;
    const int lane = tid & 31;
    const int w    = tid >> 5;
    const int wm   = (w >> 2) * 64;
    const int wn   = (w & 3) * 32;

    const int ar = tid >> 1;            // 0..127
    const int ac = (tid & 1) * 16;      // 0,16
    const int br = tid >> 3;            // 0..31
    const int bc = (tid & 7) * 16;      // 0..112

    const unsigned sA = sptr(&As[0][0]);
    const unsigned sB = sptr(&Bs[0][0]);

    float acc[4][4][4];
#pragma unroll
    for (int mi = 0; mi < 4; mi++)
#pragma unroll
        for (int ni = 0; ni < 4; ni++)
#pragma unroll
            for (int e = 0; e < 4; e++) acc[mi][ni][e] = 0.f;

    // async issue of chunk c into buffer c&1
    auto issue = [&](int c) {
        const int buf = c & 1;
        const int k0  = c * 32;
        const unsigned da = sA + (unsigned)(((buf * 128 + ar) * 40 + ac) * 2);
        const __half* pa = Ah + (size_t)(brow + ar) * K + k0 + ac;
        cp16(da,      pa);
        cp16(da + 16, pa + 8);
        const unsigned db = sB + (unsigned)(((buf * 32 + br) * 136 + bc) * 2);
        const __half* pb = Wh + (size_t)(k0 + br) * N + bcol + bc;
        cp16(db,      pb);
        cp16(db + 16, pb + 8);
        cp_commit();
    };

    const int NC = K / 32;
    issue(0);

    for (int c = 0; c < NC; c++) {
        cp_wait<0>();
        __syncthreads();
        if (c + 1 < NC) issue(c + 1);   // overlaps with compute below

        const int aoff = (c & 1) * 128;
        const int boff = (c & 1) * 32;
#pragma unroll
        for (int ks2 = 0; ks2 < 2; ks2++) {
            const int kk = ks2 * 16;
            unsigned af[4][4];
#pragma unroll
            for (int mi = 0; mi < 4; mi++)
                ldsm4(af[mi], sptr(&As[aoff + wm + mi * 16 + (lane & 15)][kk + ((lane >> 4) << 3)]));
            unsigned bfr[2][4];
#pragma unroll
            for (int np = 0; np < 2; np++) {
                const int row = boff + kk + (lane & 7) + (((lane >> 3) & 1) << 3);
                const int col = wn + np * 16 + ((lane >> 4) << 3);
                ldsm4t(bfr[np], sptr(&Bs[row][col]));
            }
#pragma unroll
            for (int mi = 0; mi < 4; mi++)
#pragma unroll
                for (int ni = 0; ni < 4; ni++)
                    mma16(acc[mi][ni], af[mi], &bfr[ni >> 1][(ni & 1) * 2]);
        }
    }

    // epilogue
    const int g = lane >> 2, q = lane & 3;
#pragma unroll
    for (int mi = 0; mi < 4; mi++) {
        const int r0 = brow + wm + mi * 16 + g;
        const int r1 = r0 + 8;
#pragma unroll
        for (int ni = 0; ni < 4; ni++) {
            const int c0 = bcol + wn + ni * 8 + 2 * q;
            const float bia0 = bias[c0], bia1 = bias[c0 + 1];
            store2<MODE>(r0, c0, acc[mi][ni][0] + bia0, acc[mi][ni][1] + bia1, Cout, N);
            store2<MODE>(r1, c0, acc[mi][ni][2] + bia0, acc[mi][ni][3] + bia1, Cout, N);
        }
    }
}

__global__ __launch_bounds__(256)
void proj_fused(const float* __restrict__ bq, const float* __restrict__ bkv)
{
    __shared__ __half As[2 * 128][40];
    __shared__ __half Bs[2 * 32][136];
    const int brow = blockIdx.y * 128;
    if (blockIdx.x < 8)
        gemm_core<0>(g_yh, g_wq, bq, nullptr, DM, DM, brow, blockIdx.x * 128, As, Bs);
    else
        gemm_core<1>(g_xh, g_wkv, bkv, nullptr, 2 * DM, DM, brow, (blockIdx.x - 8) * 128, As, Bs);
}

__global__ __launch_bounds__(256)
void gemm_o(const float* __restrict__ bias, float* __restrict__ Cout)
{
    __shared__ __half As[2 * 128][40];
    __shared__ __half Bs[2 * 32][136];
    gemm_core<2>(g_vals, g_wo, bias, Cout, DM, DM,
                 blockIdx.y * 128, blockIdx.x * 128, As, Bs);
}

// ---------------------------------------------------------------------------
// Flash attention fp16: 64 q-rows/CTA, 128 threads (4 warps x 16 rows),
// key tile 64, cp.async double-buffered K/V, base-2 softmax, mask fast-path.
// ~46KB smem, ~110 regs -> 4 CTAs/SM for phase overlap.
// ---------------------------------------------------------------------------
__global__ __launch_bounds__(128)
void attn_h(const float* __restrict__ mask)
{
    __shared__ __half qs[64][72];
    __shared__ __half ks[2 * 64][72];
    __shared__ __half vs[2 * 64][72];

    const int tid  = threadIdx.x;
    const int lane = tid & 31;
    const int w    = tid >> 5;          // 0..3
    const int g    = lane >> 2;
    const int q    = lane & 3;

    const int bh    = blockIdx.y;
    const int b     = bh >> 4;
    const int h     = bh & 15;
    const int qbase = blockIdx.x * 64;

    const __half* qg  = g_q + ((size_t)bh * SS + qbase) * HD;
    const __half* kgb = g_k + (size_t)bh * SS * HD;
    const __half* vgb = g_v + (size_t)bh * SS * HD;

    const bool use_mask = (g_mask_nz != 0);

    const int tr = tid >> 1;            // 0..63
    const int tc = (tid & 1) * 32;      // 0,32

    // async K/V tile issue into buffer kt&1 (4 x 16B each per thread)
    auto issue_kv = (void(*)(int))nullptr; (void)issue_kv;

    // issue tile 0
    {
        const __half* kp = kgb + (size_t)tr * HD + tc;
        const __half* vp = vgb + (size_t)tr * HD + tc;
#pragma unroll
        for (int i = 0; i < 4; i++) {
            cp16(sptr(&ks[tr][tc + i * 8]), kp + i * 8);
            cp16(sptr(&vs[tr][tc + i * 8]), vp + i * 8);
        }
        cp_commit();
    }

    // q tile load (synchronous; already fp16 + pre-scaled by 0.125*log2e)
    {
        const int r = tid >> 1, cs = (tid & 1) * 32;
#pragma unroll
        for (int i = 0; i < 4; i++)
            *(uint4*)&qs[r][cs + i * 8] = *(const uint4*)(qg + (size_t)r * HD + cs + i * 8);
    }

    cp_wait<0>();
    __syncthreads();

    // hoist q a-fragments (invariant)
    unsigned qa[4][4];
#pragma unroll
    for (int kk4 = 0; kk4 < 4; kk4++)
        ldsm4(qa[kk4], sptr(&qs[w * 16 + (lane & 15)][kk4 * 16 + ((lane >> 4) << 3)]));

    float oacc[8][4];
#pragma unroll
    for (int ni = 0; ni < 8; ni++)
#pragma unroll
        for (int e = 0; e < 4; e++) oacc[ni][e] = 0.f;
    float m0 = -1e30f, m1 = -1e30f, l0 = 0.f, l1 = 0.f;

    const int qrow0 = w * 16 + g;
    const int qrow1 = qrow0 + 8;
    const float* mrow0 = mask + ((size_t)b * SS + qbase + qrow0) * SS;
    const float* mrow1 = mask + ((size_t)b * SS + qbase + qrow1) * SS;

    const int NT = SS / 64;
    for (int kt = 0; kt < NT; kt++) {
        const int kbase = kt * 64;
        const int cb = (kt & 1) * 64;

        // issue next tile (overlaps compute)
        if (kt + 1 < NT) {
            const int nb = ((kt + 1) & 1) * 64;
            const __half* kp = kgb + (size_t)(kbase + 64 + tr) * HD + tc;
            const __half* vp = vgb + (size_t)(kbase + 64 + tr) * HD + tc;
#pragma unroll
            for (int i = 0; i < 4; i++) {
                cp16(sptr(&ks[nb + tr][tc + i * 8]), kp + i * 8);
                cp16(sptr(&vs[nb + tr][tc + i * 8]), vp + i * 8);
            }
            cp_commit();
        }

        // ---- S = Q K^T (16 x 64 per warp), log2-space
        float sacc[8][4];
#pragma unroll
        for (int ni = 0; ni < 8; ni++)
#pragma unroll
            for (int e = 0; e < 4; e++) sacc[ni][e] = 0.f;

#pragma unroll
        for (int kk4 = 0; kk4 < 4; kk4++) {
#pragma unroll
            for (int np = 0; np < 4; np++) {
                unsigned kb[4];
                const int rrow = cb + np * 16 + (lane & 7) + (((lane >> 4) & 1) << 3);
                const int col = kk4 * 16 + (((lane >> 3) & 1) << 3);
                ldsm4(kb, sptr(&ks[rrow][col]));
                mma16(sacc[np * 2],     qa[kk4], &kb[0]);
                mma16(sacc[np * 2 + 1], qa[kk4], &kb[2]);
            }
        }

        // ---- + mask (only when mask is nonzero anywhere)
        if (use_mask) {
#pragma unroll
            for (int ni = 0; ni < 8; ni++) {
                const int col = kbase + ni * 8 + 2 * q;
                const float2 mv0 = *(const float2*)(mrow0 + col);
                const float2 mv1 = *(const float2*)(mrow1 + col);
                sacc[ni][0] = fmaf(mv0.x, LOG2E, sacc[ni][0]);
                sacc[ni][1] = fmaf(mv0.y, LOG2E, sacc[ni][1]);
                sacc[ni][2] = fmaf(mv1.x, LOG2E, sacc[ni][2]);
                sacc[ni][3] = fmaf(mv1.y, LOG2E, sacc[ni][3]);
            }
        }

        // ---- online softmax (base-2)
        float mx0 = -1e30f, mx1 = -1e30f;
#pragma unroll
        for (int ni = 0; ni < 8; ni++) {
            mx0 = fmaxf(mx0, fmaxf(sacc[ni][0], sacc[ni][1]));
            mx1 = fmaxf(mx1, fmaxf(sacc[ni][2], sacc[ni][3]));
        }
        mx0 = fmaxf(mx0, __shfl_xor_sync(0xffffffffu, mx0, 1));
        mx0 = fmaxf(mx0, __shfl_xor_sync(0xffffffffu, mx0, 2));
        mx1 = fmaxf(mx1, __shfl_xor_sync(0xffffffffu, mx1, 1));
        mx1 = fmaxf(mx1, __shfl_xor_sync(0xffffffffu, mx1, 2));

        const float mn0 = fmaxf(m0, mx0);
        const float mn1 = fmaxf(m1, mx1);
        const float al0 = ex2(m0 - mn0);
        const float al1 = ex2(m1 - mn1);
        float sum0 = 0.f, sum1 = 0.f;
#pragma unroll
        for (int ni = 0; ni < 8; ni++) {
            sacc[ni][0] = ex2(sacc[ni][0] - mn0); sum0 += sacc[ni][0];
            sacc[ni][1] = ex2(sacc[ni][1] - mn0); sum0 += sacc[ni][1];
            sacc[ni][2] = ex2(sacc[ni][2] - mn1); sum1 += sacc[ni][2];
            sacc[ni][3] = ex2(sacc[ni][3] - mn1); sum1 += sacc[ni][3];
        }
        sum0 += __shfl_xor_sync(0xffffffffu, sum0, 1);
        sum0 += __shfl_xor_sync(0xffffffffu, sum0, 2);
        sum1 += __shfl_xor_sync(0xffffffffu, sum1, 1);
        sum1 += __shfl_xor_sync(0xffffffffu, sum1, 2);
        l0 = l0 * al0 + sum0; m0 = mn0;
        l1 = l1 * al1 + sum1; m1 = mn1;

#pragma unroll
        for (int ni = 0; ni < 8; ni++) {
            oacc[ni][0] *= al0; oacc[ni][1] *= al0;
            oacc[ni][2] *= al1; oacc[ni][3] *= al1;
        }

        // ---- O += P V (P straight from registers)
#pragma unroll
        for (int j = 0; j < 4; j++) {
            unsigned paf[4];
            paf[0] = pkh(sacc[2 * j][0],     sacc[2 * j][1]);
            paf[1] = pkh(sacc[2 * j][2],     sacc[2 * j][3]);
            paf[2] = pkh(sacc[2 * j + 1][0], sacc[2 * j + 1][1]);
            paf[3] = pkh(sacc[2 * j + 1][2], sacc[2 * j + 1][3]);
#pragma unroll
            for (int np = 0; np < 4; np++) {
                unsigned vb[4];
                const int rrow = cb + j * 16 + (lane & 7) + (((lane >> 3) & 1) << 3);
                const int col = np * 16 + ((lane >> 4) << 3);
                ldsm4t(vb, sptr(&vs[rrow][col]));
                mma16(oacc[np * 2],     paf, &vb[0]);
                mma16(oacc[np * 2 + 1], paf, &vb[2]);
            }
        }

        if (kt + 1 < NT) {
            cp_wait<0>();
            __syncthreads();
        }
    }

    // epilogue -> g_vals
    const float inv0 = 1.0f / l0;
    const float inv1 = 1.0f / l1;
    __half* orow0 = g_vals + ((size_t)b * SS + qbase + qrow0) * DM + h * HD;
    __half* orow1 = g_vals + ((size_t)b * SS + qbase + qrow1) * DM + h * HD;
#pragma unroll
    for (int ni = 0; ni < 8; ni++) {
        const int col = ni * 8 + 2 * q;
        *(unsigned*)&orow0[col] = pkh(oacc[ni][0] * inv0, oacc[ni][1] * inv0);
        *(unsigned*)&orow1[col] = pkh(oacc[ni][2] * inv1, oacc[ni][3] * inv1);
    }
}

// ---------------------------------------------------------------------------
extern "C" void kernel_launch(void* const* d_in, const int* in_sizes, int n_in,
                              void* d_out, int out_size)
{
    const float* x    = (const float*)d_in[0];
    const float* y    = (const float*)d_in[1];
    const float* mask = (const float*)d_in[2];
    const float* Wkv  = (const float*)d_in[3];
    const float* bkv  = (const float*)d_in[4];
    const float* Wq   = (const float*)d_in[5];
    const float* bq   = (const float*)d_in[6];
    const float* Wo   = (const float*)d_in[7];
    const float* bo   = (const float*)d_in[8];
    float* out = (float*)d_out;

    void *xh, *yh, *wq, *wkv, *wo;
    cudaGetSymbolAddress(&xh, g_xh);
    cudaGetSymbolAddress(&yh, g_yh);
    cudaGetSymbolAddress(&wq, g_wq);
    cudaGetSymbolAddress(&wkv, g_wkv);
    cudaGetSymbolAddress(&wo, g_wo);

    const dim3 blk(256);
    const int M = BB * SS;  // 4096

    // mask zero-check
    flag_zero<<<1, 1>>>();
    const int mn4 = BB * SS * SS / 4;
    mask_check<<<(mn4 + 255) / 256, blk>>>((const float4*)mask, mn4);

    // fp32 -> fp16 pre-passes
    cvt_h<<<(BB * SS * DM / 4 + 255) / 256, blk>>>((const float4*)x, (uint2*)xh, BB * SS * DM / 4, 1.f);
    cvt_h<<<(BB * SS * DM / 4 + 255) / 256, blk>>>((const float4*)y, (uint2*)yh, BB * SS * DM / 4, 1.f);
    cvt_h<<<(DM * DM / 4 + 255) / 256, blk>>>((const float4*)Wq, (uint2*)wq, DM * DM / 4, 1.f);
    cvt_h<<<(DM * 2 * DM / 4 + 255) / 256, blk>>>((const float4*)Wkv, (uint2*)wkv, DM * 2 * DM / 4, 1.f);
    cvt_h<<<(DM * DM / 4 + 255) / 256, blk>>>((const float4*)Wo, (uint2*)wo, DM * DM / 4, 1.f);

    // fused q + kv projection
    proj_fused<<<dim3(24, M / 128), blk>>>(bq, bkv);

    // attention: 64 q-rows per CTA, 128 threads
    attn_h<<<dim3(SS / 64, BB * NH), dim3(128)>>>(mask);

    // output projection
    gemm_o<<<dim3(DM / 128, M / 128), blk>>>(bo, out);
}